// round 10
// baseline (speedup 1.0000x reference)
#include <cuda_runtime.h>
#include <float.h>
#include <stdint.h>

// SparseSoftmax: masked softmax over last axis of (32, 2048, 2048) fp32
// with int32 mask (mask = OD != 0). Fully-masked rows -> zeros.
//
// R10: 64 threads/row, 32 elements/thread via Blackwell 256-bit vector ops:
// 4x ld.global.nc.v8.f32 + 4x ld.global.nc.v8.b32 + 4x st.global.v8.f32.
// Doubles per-warp bytes-in-flight vs R9 (the only lever that has moved this
// kernel); mask folded right after each load pair to recycle mask registers.

#define ROW_LEN 2048
#define THREADS 64
#define EPT     32
#define NWARPS  (THREADS / 32)   // 2

__device__ __forceinline__ void ldg256_f32(float* r, const float* p) {
    asm volatile(
        "ld.global.nc.v8.f32 {%0,%1,%2,%3,%4,%5,%6,%7}, [%8];"
        : "=f"(r[0]), "=f"(r[1]), "=f"(r[2]), "=f"(r[3]),
          "=f"(r[4]), "=f"(r[5]), "=f"(r[6]), "=f"(r[7])
        : "l"(p));
}

__device__ __forceinline__ void ldg256_s32(int* r, const int* p) {
    asm volatile(
        "ld.global.nc.v8.b32 {%0,%1,%2,%3,%4,%5,%6,%7}, [%8];"
        : "=r"(r[0]), "=r"(r[1]), "=r"(r[2]), "=r"(r[3]),
          "=r"(r[4]), "=r"(r[5]), "=r"(r[6]), "=r"(r[7])
        : "l"(p));
}

__device__ __forceinline__ void stg256_f32(float* p, const float* r) {
    asm volatile(
        "st.global.v8.f32 [%0], {%1,%2,%3,%4,%5,%6,%7,%8};"
        :: "l"(p),
           "f"(r[0]), "f"(r[1]), "f"(r[2]), "f"(r[3]),
           "f"(r[4]), "f"(r[5]), "f"(r[6]), "f"(r[7])
        : "memory");
}

__global__ __launch_bounds__(THREADS)
void sparse_softmax_kernel(const float* __restrict__ f,
                           const int* __restrict__ od,
                           float* __restrict__ out)
{
    const int row = blockIdx.x;
    const size_t base = (size_t)row * ROW_LEN;

    const int t    = threadIdx.x;
    const int warp = t >> 5;
    const int lane = t & 31;
    const float NEG_INF = __int_as_float(0xff800000);

    // Thread t covers 4 chunks of 8 elements, strided by 512.
    const float* fp = f  + base + (size_t)t * 8;
    const int*   mp = od + base + (size_t)t * 8;

    float vals[EPT];
    int   msk [EPT];
    // Front-batch all 8 LDG.256s so they're in flight together.
    ldg256_f32(vals,      fp);
    ldg256_f32(vals +  8, fp + 512);
    ldg256_f32(vals + 16, fp + 1024);
    ldg256_f32(vals + 24, fp + 1536);
    ldg256_s32(msk,       mp);
    ldg256_s32(msk  +  8, mp + 512);
    ldg256_s32(msk  + 16, mp + 1024);
    ldg256_s32(msk  + 24, mp + 1536);

    // Fold mask into values: masked-out lanes become -inf (mask regs die here).
    #pragma unroll
    for (int i = 0; i < EPT; i++)
        vals[i] = msk[i] ? vals[i] : NEG_INF;

    __shared__ float smax[NWARPS];
    __shared__ float ssum[NWARPS];

    // --- max reduce (masked lanes are -inf, harmless) ---
    float mx = NEG_INF;
    #pragma unroll
    for (int i = 0; i < EPT; i++) mx = fmaxf(mx, vals[i]);
    #pragma unroll
    for (int o = 16; o > 0; o >>= 1)
        mx = fmaxf(mx, __shfl_xor_sync(0xffffffffu, mx, o));
    if (lane == 0) smax[warp] = mx;
    __syncthreads();

    float rowmax = fmaxf(smax[0], smax[1]);
    // Fully-masked row: rowmax = -inf would give NaN in (v - rowmax); clamp.
    if (!(rowmax > NEG_INF)) rowmax = 0.0f;

    // --- exp + sum; exp(-inf - rowmax) = 0 on masked lanes ---
    float sum = 0.0f;
    #pragma unroll
    for (int i = 0; i < EPT; i++) {
        vals[i] = __expf(vals[i] - rowmax);   // overwrite in place: p[i]
        sum += vals[i];
    }
    #pragma unroll
    for (int o = 16; o > 0; o >>= 1)
        sum += __shfl_xor_sync(0xffffffffu, sum, o);
    if (lane == 0) ssum[warp] = sum;
    __syncthreads();

    float s = ssum[0] + ssum[1];
    const float inv = (s > 0.0f) ? (1.0f / s) : 0.0f;   // fully-masked -> zeros

    // --- normalize + four 256-bit stores ---
    #pragma unroll
    for (int i = 0; i < EPT; i++) vals[i] *= inv;

    float* op = out + base + (size_t)t * 8;
    stg256_f32(op,        vals);
    stg256_f32(op +  512, vals + 8);
    stg256_f32(op + 1024, vals + 16);
    stg256_f32(op + 1536, vals + 24);
}

extern "C" void kernel_launch(void* const* d_in, const int* in_sizes, int n_in,
                              void* d_out, int out_size)
{
    const float* features = (const float*)d_in[0];
    const int*   OD       = (const int*)d_in[1];
    float*       out      = (float*)d_out;

    const int rows = in_sizes[0] / ROW_LEN;   // 32*2048 = 65536
    sparse_softmax_kernel<<<rows, THREADS>>>(features, OD, out);
}